// round 14
// baseline (speedup 1.0000x reference)
#include <cuda_runtime.h>
#include <cuda_fp16.h>
#include <math.h>
#include <stdint.h>

// ---------------------------------------------------------------------------
// Problem constants
// ---------------------------------------------------------------------------
#define BATCH 2
#define SEQ   2048
#define DIM   2048
#define NHEAD 32
#define DHEAD 64
#define FFN   8192
#define LDWIN 18560
#define HCOLS 10368
#define QKV   2176
#define OUTK  10240
#define MTOK  (BATCH*SEQ)
#define LN_EPS 1e-5f
#define QSCALE 0.125f
#define LOG2E  1.4426950408889634f

// ---------------------------------------------------------------------------
// Scratch (device globals)
// ---------------------------------------------------------------------------
__device__ float g_xn[(size_t)MTOK * DIM];
__device__ float g_h[(size_t)MTOK * QKV];
__device__ float g_ap[(size_t)MTOK * DIM];      // attn-slice partial of GEMM2
__device__ __half g_a1[(size_t)MTOK * DIM];
__device__ __half g_w1[(size_t)HCOLS * DIM];
__device__ __half g_a2[(size_t)MTOK * OUTK];
__device__ __half g_w2[(size_t)DIM * OUTK];
__device__ __half g_q16[(size_t)MTOK * DIM];
__device__ __half g_k16[(size_t)MTOK * DHEAD];
__device__ __half g_vT[(size_t)MTOK * DHEAD];

// ---------------------------------------------------------------------------
// PTX helpers
// ---------------------------------------------------------------------------
__device__ __forceinline__ uint32_t smem_u32(const void* p) {
    uint32_t a;
    asm("{ .reg .u64 t; cvta.to.shared.u64 t, %1; cvt.u32.u64 %0, t; }" : "=r"(a) : "l"(p));
    return a;
}
#define CP_ASYNC16(sa, gp) \
    asm volatile("cp.async.cg.shared.global [%0], [%1], 16;" :: "r"(sa), "l"(gp))
#define CP_COMMIT() asm volatile("cp.async.commit_group;" ::: "memory")
#define CP_WAIT(n)  asm volatile("cp.async.wait_group %0;" :: "n"(n) : "memory")

#define LDSM_X4(r0, r1, r2, r3, addr) \
    asm volatile("ldmatrix.sync.aligned.m8n8.x4.shared.b16 {%0,%1,%2,%3}, [%4];" \
        : "=r"(r0), "=r"(r1), "=r"(r2), "=r"(r3) : "r"(addr))

#define MMA16816(d, a0, a1, a2, a3, b0, b1) \
    asm volatile("mma.sync.aligned.m16n8k16.row.col.f32.f16.f16.f32 " \
        "{%0,%1,%2,%3}, {%4,%5,%6,%7}, {%8,%9}, {%0,%1,%2,%3};" \
        : "+f"((d)[0]), "+f"((d)[1]), "+f"((d)[2]), "+f"((d)[3]) \
        : "r"(a0), "r"(a1), "r"(a2), "r"(a3), "r"(b0), "r"(b1))

__device__ __forceinline__ __half2 h2(float x, float y) {
    return __halves2half2(__float2half_rn(x), __float2half_rn(y));
}
__device__ __forceinline__ uint32_t packh2(float x, float y) {
    __half2 v = __floats2half2_rn(x, y);
    return *reinterpret_cast<uint32_t*>(&v);
}

__device__ __forceinline__ float exp2_poly(float t) {
    t = fmaxf(t, -60.0f);
    float fi = floorf(t);
    float f = t - fi;
    float p = 1.3333558e-3f;
    p = fmaf(p, f, 9.6181291e-3f);
    p = fmaf(p, f, 5.5504109e-2f);
    p = fmaf(p, f, 2.4022651e-1f);
    p = fmaf(p, f, 6.9314718e-1f);
    p = fmaf(p, f, 1.0f);
    float s = __int_as_float(((int)fi + 127) << 23);
    return s * p;
}

// ---------------------------------------------------------------------------
// Kernel: LayerNorm -> xn (fp32 residual) + a1 (fp16 GEMM1 operand)
// ---------------------------------------------------------------------------
__global__ void ln_split_kernel(const float* __restrict__ x,
                                const float* __restrict__ gamma,
                                const float* __restrict__ beta,
                                float* __restrict__ xn,
                                __half* __restrict__ a1) {
    int row = blockIdx.x;
    int tid = threadIdx.x;
    const float4* xr = reinterpret_cast<const float4*>(x + (size_t)row * DIM);
    float4 a = xr[tid];
    float4 b = xr[tid + 256];
    float s  = a.x + a.y + a.z + a.w + b.x + b.y + b.z + b.w;
    float s2 = a.x*a.x + a.y*a.y + a.z*a.z + a.w*a.w
             + b.x*b.x + b.y*b.y + b.z*b.z + b.w*b.w;
    #pragma unroll
    for (int off = 16; off > 0; off >>= 1) {
        s  += __shfl_xor_sync(0xffffffffu, s,  off);
        s2 += __shfl_xor_sync(0xffffffffu, s2, off);
    }
    __shared__ float ss[8], ss2[8];
    int wid = tid >> 5, lane = tid & 31;
    if (lane == 0) { ss[wid] = s; ss2[wid] = s2; }
    __syncthreads();
    s  = ss[0] + ss[1] + ss[2] + ss[3] + ss[4] + ss[5] + ss[6] + ss[7];
    s2 = ss2[0]+ ss2[1]+ ss2[2]+ ss2[3]+ ss2[4]+ ss2[5]+ ss2[6]+ ss2[7];
    float mean = s * (1.0f / DIM);
    float var  = s2 * (1.0f / DIM) - mean * mean;
    float rstd = rsqrtf(var + LN_EPS);

    const float4* g4 = reinterpret_cast<const float4*>(gamma);
    const float4* b4 = reinterpret_cast<const float4*>(beta);
    float4 g0 = g4[tid], g1 = g4[tid + 256];
    float4 be0 = b4[tid], be1 = b4[tid + 256];
    float4 o0, o1;
    o0.x = (a.x - mean) * rstd * g0.x + be0.x;
    o0.y = (a.y - mean) * rstd * g0.y + be0.y;
    o0.z = (a.z - mean) * rstd * g0.z + be0.z;
    o0.w = (a.w - mean) * rstd * g0.w + be0.w;
    o1.x = (b.x - mean) * rstd * g1.x + be1.x;
    o1.y = (b.y - mean) * rstd * g1.y + be1.y;
    o1.z = (b.z - mean) * rstd * g1.z + be1.z;
    o1.w = (b.w - mean) * rstd * g1.w + be1.w;
    float4* o4 = reinterpret_cast<float4*>(xn + (size_t)row * DIM);
    o4[tid] = o0;
    o4[tid + 256] = o1;

    __half2* ph = reinterpret_cast<__half2*>(a1 + (size_t)row * DIM);
    ph[tid*2+0]   = h2(o0.x, o0.y);
    ph[tid*2+1]   = h2(o0.z, o0.w);
    ph[tid*2+512] = h2(o1.x, o1.y);
    ph[tid*2+513] = h2(o1.z, o1.w);
}

// ---------------------------------------------------------------------------
// Kernel: transpose + fp16 convert, 64x64 tile, vectorized.
// dst[n][k] = src[k][n]. Block (16,16).
// ---------------------------------------------------------------------------
__global__ void tsplit_kernel(const float* __restrict__ src, int ld_src,
                              __half* __restrict__ dst, int ld_dst) {
    __shared__ float t[64][65];
    int n0 = blockIdx.x * 64, k0 = blockIdx.y * 64;
    int tx = threadIdx.x, ty = threadIdx.y;    // 16 x 16
    #pragma unroll
    for (int i = 0; i < 4; i++) {
        float4 v = *reinterpret_cast<const float4*>(
            src + (size_t)(k0 + ty + 16*i) * ld_src + n0 + tx*4);
        t[ty + 16*i][tx*4+0] = v.x;
        t[ty + 16*i][tx*4+1] = v.y;
        t[ty + 16*i][tx*4+2] = v.z;
        t[ty + 16*i][tx*4+3] = v.w;
    }
    __syncthreads();
    #pragma unroll
    for (int i = 0; i < 4; i++) {
        int n = ty + 16*i;
        uint2 u;
        u.x = packh2(t[tx*4+0][n], t[tx*4+1][n]);
        u.y = packh2(t[tx*4+2][n], t[tx*4+3][n]);
        *reinterpret_cast<uint2*>(dst + (size_t)(n0 + n) * ld_dst + k0 + tx*4) = u;
    }
}

// ---------------------------------------------------------------------------
// Kernel: out += ap (fp32, vectorized)
// ---------------------------------------------------------------------------
__global__ void add_kernel(float* __restrict__ out, const float* __restrict__ ap) {
    size_t i = ((size_t)blockIdx.x * 256 + threadIdx.x) * 4;
    float4 o = *reinterpret_cast<float4*>(out + i);
    float4 a = *reinterpret_cast<const float4*>(ap + i);
    o.x += a.x; o.y += a.y; o.z += a.z; o.w += a.w;
    *reinterpret_cast<float4*>(out + i) = o;
}

// ---------------------------------------------------------------------------
// Tensor-core GEMM (R9 config: BK=32, SROWB=80, NSTAGE=4, 256 thr, 2 CTAs/SM).
// ncol0: N-offset of this launch's tile range (B addressing + epilogue).
// MODE 0: (n0+ncol0) <  QKV -> fp32 to Cf (ld ldc);
//         (n0+ncol0) >= QKV -> fp16 to Ch at col (n0+ncol0-128).
// MODE 1: fp32 out = acc + resid.
// ---------------------------------------------------------------------------
#define BK     32
#define SROWB  80
#define OFF_B  10240
#define STAGEB 20480
#define NSTAGE 4

template <int MODE>
__global__ __launch_bounds__(256, 2) void gemm_mma(
        const __half* __restrict__ A, const __half* __restrict__ B,
        float* __restrict__ Cf, __half* __restrict__ Ch,
        int K, int ld, int ldc, int ncol0, const float* __restrict__ resid) {
    extern __shared__ __align__(16) char dsm[];
    uint32_t sbase = smem_u32(dsm);

    int tid  = threadIdx.x;
    int wid  = tid >> 5;
    int lane = tid & 31;
    int wm   = wid & 3;
    int wn   = wid >> 2;

    int m0 = blockIdx.x * 128;
    int n0 = blockIdx.y * 128 + ncol0;

    uint32_t sO[2]; size_t gO[2];
    #pragma unroll
    for (int i = 0; i < 2; i++) {
        int idx = tid + i * 256;
        int row = idx >> 2, c = idx & 3;
        sO[i] = (uint32_t)(row * SROWB + c * 16);
        gO[i] = (size_t)row * ld + c * 8;
    }
    const __half* gA = A + (size_t)m0 * ld;
    const __half* gB = B + (size_t)n0 * ld;

    const int NC = K / BK;

    auto load_chunk = [&](int c) {
        uint32_t base = sbase + (uint32_t)(c % NSTAGE) * STAGEB;
        size_t co = (size_t)c * BK;
        #pragma unroll
        for (int i = 0; i < 2; i++) {
            CP_ASYNC16(base + sO[i],         (const void*)(gA + gO[i] + co));
            CP_ASYNC16(base + OFF_B + sO[i], (const void*)(gB + gO[i] + co));
        }
    };

    float acc[2][8][4];
    #pragma unroll
    for (int i = 0; i < 2; i++)
        #pragma unroll
        for (int j = 0; j < 8; j++)
            #pragma unroll
            for (int v = 0; v < 4; v++) acc[i][j][v] = 0.0f;

    #pragma unroll
    for (int c = 0; c < NSTAGE - 1; c++) { load_chunk(c); CP_COMMIT(); }

    uint32_t aBase = (uint32_t)((wm * 32 + (lane & 15)) * SROWB + (lane >> 4) * 16);
    uint32_t bBase = (uint32_t)((wn * 64 + (lane & 15)) * SROWB + (lane >> 4) * 16);

    for (int c = 0; c < NC; c++) {
        CP_WAIT(NSTAGE - 2);
        __syncthreads();
        if (c + NSTAGE - 1 < NC) load_chunk(c + NSTAGE - 1);
        CP_COMMIT();

        uint32_t buf = sbase + (uint32_t)(c % NSTAGE) * STAGEB;

        #pragma unroll
        for (int ks = 0; ks < 2; ks++) {
            uint32_t aF[2][4];
            #pragma unroll
            for (int mt = 0; mt < 2; mt++) {
                uint32_t ad = buf + aBase + mt * (16 * SROWB) + ks * 32;
                LDSM_X4(aF[mt][0], aF[mt][1], aF[mt][2], aF[mt][3], ad);
            }
            #pragma unroll
            for (int g = 0; g < 4; g++) {
                uint32_t bd = buf + OFF_B + bBase + g * (16 * SROWB) + ks * 32;
                uint32_t bf[4];
                LDSM_X4(bf[0], bf[1], bf[2], bf[3], bd);
                int nt0 = 2 * g, nt1 = 2 * g + 1;
                MMA16816(acc[0][nt0], aF[0][0], aF[0][1], aF[0][2], aF[0][3], bf[0], bf[2]);
                MMA16816(acc[0][nt1], aF[0][0], aF[0][1], aF[0][2], aF[0][3], bf[1], bf[3]);
                MMA16816(acc[1][nt0], aF[1][0], aF[1][1], aF[1][2], aF[1][3], bf[0], bf[2]);
                MMA16816(acc[1][nt1], aF[1][0], aF[1][1], aF[1][2], aF[1][3], bf[1], bf[3]);
            }
        }
    }

    int g = lane >> 2, q = lane & 3;
    if (MODE == 0 && n0 >= QKV) {
        #pragma unroll
        for (int mt = 0; mt < 2; mt++) {
            #pragma unroll
            for (int nt = 0; nt < 8; nt++) {
                int rowm = m0 + wm * 32 + mt * 16 + g;
                int coln = n0 - 128 + wn * 64 + nt * 8 + q * 2;
                *reinterpret_cast<__half2*>(Ch + (size_t)rowm * OUTK + coln) =
                    h2(acc[mt][nt][0], acc[mt][nt][1]);
                *reinterpret_cast<__half2*>(Ch + (size_t)(rowm + 8) * OUTK + coln) =
                    h2(acc[mt][nt][2], acc[mt][nt][3]);
            }
        }
        return;
    }
    #pragma unroll
    for (int mt = 0; mt < 2; mt++) {
        #pragma unroll
        for (int nt = 0; nt < 8; nt++) {
            int rowm = m0 + wm * 32 + mt * 16 + g;
            int coln = n0 + wn * 64 + nt * 8 + q * 2;
            float* p0 = Cf + (size_t)rowm * ldc + coln;
            float* p1 = Cf + (size_t)(rowm + 8) * ldc + coln;
            float2 v0 = make_float2(acc[mt][nt][0], acc[mt][nt][1]);
            float2 v1 = make_float2(acc[mt][nt][2], acc[mt][nt][3]);
            if (MODE == 1) {
                const float2 r0 = *reinterpret_cast<const float2*>(resid + (size_t)rowm * ldc + coln);
                const float2 r1 = *reinterpret_cast<const float2*>(resid + (size_t)(rowm + 8) * ldc + coln);
                v0.x += r0.x; v0.y += r0.y;
                v1.x += r1.x; v1.y += r1.y;
            }
            *reinterpret_cast<float2*>(p0) = v0;
            *reinterpret_cast<float2*>(p1) = v1;
        }
    }
}

// ---------------------------------------------------------------------------
// Kernel: qkv prep (sincos once per (s,c), shared across heads).
// ---------------------------------------------------------------------------
__global__ __launch_bounds__(128) void qkv_prep_kernel(
        const float* __restrict__ h,
        __half* __restrict__ q16, __half* __restrict__ k16,
        __half* __restrict__ vT) {
    __shared__ float scs[32], ssn[32];
    int row = blockIdx.x;
    int b = row >> 11;
    int s = row & (SEQ - 1);
    const float* hp = h + (size_t)row * QKV;
    int tid = threadIdx.x;

    if (tid < 32) {
        int c = tid;
        float inv = exp2f(-(float)c * (13.287712379549449f / 32.0f));
        float ang = (float)s * inv;
        float sn, cs;
        sincosf(ang, &sn, &cs);
        scs[c] = cs; ssn[c] = sn;
        float ka = hp[2048 + c], kb = hp[2048 + c + 32];
        __half* kd = k16 + ((size_t)b * SEQ + s) * DHEAD;
        kd[c]      = __float2half_rn(ka * cs - kb * sn);
        kd[c + 32] = __float2half_rn(kb * cs + ka * sn);
    }
    if (tid >= 64) {
        int d = tid - 64;
        vT[((size_t)b * DHEAD + d) * SEQ + s] = __float2half_rn(hp[2112 + d]);
    }
    __syncthreads();

    const float scl = QSCALE * LOG2E;
    for (int i = tid; i < 1024; i += 128) {
        int hd = i >> 5, c = i & 31;
        float cs = scs[c], sn = ssn[c];
        float qa = hp[hd * 64 + c], qb = hp[hd * 64 + c + 32];
        __half* qd = q16 + ((size_t)(b * NHEAD + hd) * SEQ + s) * DHEAD;
        qd[c]      = __float2half_rn((qa * cs - qb * sn) * scl);
        qd[c + 32] = __float2half_rn((qb * cs + qa * sn) * scl);
    }
}

// ---------------------------------------------------------------------------
// Tensor-core causal MQA flash attention (64-row Q tile).
// ---------------------------------------------------------------------------
#define FROWB 144

__global__ __launch_bounds__(128) void fmha_kernel(
        const __half* __restrict__ q16, const __half* __restrict__ k16,
        const __half* __restrict__ vT, __half* __restrict__ a2) {
    __shared__ __half sQ[64 * 72];
    __shared__ __half sK[2][64 * 72];
    __shared__ __half sV[2][64 * 72];

    int tid = threadIdx.x;
    int w = tid >> 5, lane = tid & 31;
    int g = lane >> 2, t = lane & 3;
    int qt = (int)gridDim.x - 1 - (int)blockIdx.x;
    int head = blockIdx.y;
    int b = blockIdx.z;

    const __half* gQ = q16 + ((size_t)(b * NHEAD + head) * SEQ + qt * 64) * DHEAD;
    const __half* gK = k16 + (size_t)b * SEQ * DHEAD;
    const __half* gV = vT + (size_t)b * DHEAD * SEQ;

    uint32_t sqa = smem_u32(sQ);
    uint32_t ska[2] = {smem_u32(sK[0]), smem_u32(sK[1])};
    uint32_t sva[2] = {smem_u32(sV[0]), smem_u32(sV[1])};

    auto load_kv = [&](int kt2, int buf2) {
        #pragma unroll
        for (int i = 0; i < 4; i++) {
            int idx = tid + i * 128;
            int r = idx >> 3, c = idx & 7;
            uint32_t so = (uint32_t)(r * FROWB + c * 16);
            CP_ASYNC16(ska[buf2] + so, (const void*)(gK + (size_t)(kt2 * 64 + r) * DHEAD + c * 8));
            CP_ASYNC16(sva[buf2] + so, (const void*)(gV + (size_t)r * SEQ + kt2 * 64 + c * 8));
        }
    };

    #pragma unroll
    for (int i = 0; i < 4; i++) {
        int idx = tid + i * 128;
        int r = idx >> 3, c = idx & 7;
        uint32_t so = (uint32_t)(r * FROWB + c * 16);
        CP_ASYNC16(sqa + so, (const void*)(gQ + (size_t)r * DHEAD + c * 8));
    }
    load_kv(0, 0);
    CP_COMMIT();
    CP_WAIT(0);
    __syncthreads();

    uint32_t aBase = (uint32_t)((w * 16 + (lane & 15)) * FROWB + (lane >> 4) * 16);
    uint32_t qa[4][4];
    #pragma unroll
    for (int ks = 0; ks < 4; ks++)
        LDSM_X4(qa[ks][0], qa[ks][1], qa[ks][2], qa[ks][3], sqa + aBase + ks * 32);

    uint32_t bBase = (uint32_t)((lane & 15) * FROWB + (lane >> 4) * 16);

    float o[8][4];
    #pragma unroll
    for (int n = 0; n < 8; n++)
        #pragma unroll
        for (int j = 0; j < 4; j++) o[n][j] = 0.0f;
    float m0 = -1e30f, m1 = -1e30f, l0 = 0.0f, l1 = 0.0f;

    for (int kt = 0; kt <= qt; kt++) {
        int buf = kt & 1;
        if (kt > 0) { CP_WAIT(0); __syncthreads(); }
        if (kt + 1 <= qt) { load_kv(kt + 1, buf ^ 1); CP_COMMIT(); }

        float s[8][4];
        #pragma unroll
        for (int n = 0; n < 8; n++)
            #pragma unroll
            for (int j = 0; j < 4; j++) s[n][j] = 0.0f;
        #pragma unroll
        for (int ng = 0; ng < 4; ng++) {
            #pragma unroll
            for (int ks = 0; ks < 4; ks++) {
                uint32_t bf[4];
                LDSM_X4(bf[0], bf[1], bf[2], bf[3],
                        ska[buf] + (uint32_t)(ng * 16 * FROWB) + bBase + ks * 32);
                MMA16816(s[2*ng],   qa[ks][0], qa[ks][1], qa[ks][2], qa[ks][3], bf[0], bf[2]);
                MMA16816(s[2*ng+1], qa[ks][0], qa[ks][1], qa[ks][2], qa[ks][3], bf[1], bf[3]);
            }
        }

        if (kt == qt) {
            int r0 = w * 16 + g;
            #pragma unroll
            for (int n = 0; n < 8; n++) {
                int c0 = n * 8 + 2 * t;
                if (c0 > r0)         s[n][0] = -1e30f;
                if (c0 + 1 > r0)     s[n][1] = -1e30f;
                if (c0 > r0 + 8)     s[n][2] = -1e30f;
                if (c0 + 1 > r0 + 8) s[n][3] = -1e30f;
            }
        }

        float tm0 = -1e30f, tm1 = -1e30f;
        #pragma unroll
        for (int n = 0; n < 8; n++) {
            tm0 = fmaxf(tm0, fmaxf(s[n][0], s[n][1]));
            tm1 = fmaxf(tm1, fmaxf(s[n][2], s[n][3]));
        }
        tm0 = fmaxf(tm0, __shfl_xor_sync(0xffffffffu, tm0, 1));
        tm0 = fmaxf(tm0, __shfl_xor_sync(0xffffffffu, tm0, 2));
        tm1 = fmaxf(tm1, __shfl_xor_sync(0xffffffffu, tm1, 1));
        tm1 = fmaxf(tm1, __shfl_xor_sync(0xffffffffu, tm1, 2));
        float mn0 = fmaxf(m0, tm0), mn1 = fmaxf(m1, tm1);
        float sc0 = exp2_poly(m0 - mn0), sc1 = exp2_poly(m1 - mn1);
        m0 = mn0; m1 = mn1;
        float ts0 = 0.0f, ts1 = 0.0f;
        #pragma unroll
        for (int n = 0; n < 8; n++) {
            s[n][0] = exp2_poly(s[n][0] - mn0);
            s[n][1] = exp2_poly(s[n][1] - mn0);
            s[n][2] = exp2_poly(s[n][2] - mn1);
            s[n][3] = exp2_poly(s[n][3] - mn1);
            ts0 += s[n][0] + s[n][1];
            ts1 += s[n][2] + s[n][3];
        }
        ts0 += __shfl_xor_sync(0xffffffffu, ts0, 1);
        ts0 += __shfl_xor_sync(0xffffffffu, ts0, 2);
        ts1 += __shfl_xor_sync(0xffffffffu, ts1, 1);
        ts1 += __shfl_xor_sync(0xffffffffu, ts1, 2);
        l0 = l0 * sc0 + ts0;
        l1 = l1 * sc1 + ts1;
        #pragma unroll
        for (int n = 0; n < 8; n++) {
            o[n][0] *= sc0; o[n][1] *= sc0;
            o[n][2] *= sc1; o[n][3] *= sc1;
        }

        uint32_t pa[4][4];
        #pragma unroll
        for (int kk = 0; kk < 4; kk++) {
            pa[kk][0] = packh2(s[2*kk][0],   s[2*kk][1]);
            pa[kk][1] = packh2(s[2*kk][2],   s[2*kk][3]);
            pa[kk][2] = packh2(s[2*kk+1][0], s[2*kk+1][1]);
            pa[kk][3] = packh2(s[2*kk+1][2], s[2*kk+1][3]);
        }

        #pragma unroll
        for (int ng = 0; ng < 4; ng++) {
            #pragma unroll
            for (int kk = 0; kk < 4; kk++) {
                uint32_t bf[4];
                LDSM_X4(bf[0], bf[1], bf[2], bf[3],
                        sva[buf] + (uint32_t)(ng * 16 * FROWB) + bBase + kk * 32);
                MMA16816(o[2*ng],   pa[kk][0], pa[kk][1], pa[kk][2], pa[kk][3], bf[0], bf[2]);
                MMA16816(o[2*ng+1], pa[kk][0], pa[kk][1], pa[kk][2], pa[kk][3], bf[1], bf[3]);
            }
        }
    }

    float inv0 = 1.0f / l0, inv1 = 1.0f / l1;
    int row0 = qt * 64 + w * 16 + g;
    size_t t0 = ((size_t)b * SEQ + row0) * OUTK + head * 64;
    size_t t1 = t0 + (size_t)8 * OUTK;
    #pragma unroll
    for (int n = 0; n < 8; n++) {
        int coff = n * 8 + 2 * t;
        *reinterpret_cast<__half2*>(a2 + t0 + coff) = h2(o[n][0] * inv0, o[n][1] * inv0);
        *reinterpret_cast<__half2*>(a2 + t1 + coff) = h2(o[n][2] * inv1, o[n][3] * inv1);
    }
}

// ---------------------------------------------------------------------------
extern "C" void kernel_launch(void* const* d_in, const int* in_sizes, int n_in,
                              void* d_out, int out_size) {
    const float* x     = (const float*)d_in[0];
    const float* W_in  = (const float*)d_in[1];
    const float* W_out = (const float*)d_in[2];
    const float* gamma = (const float*)d_in[3];
    const float* beta  = (const float*)d_in[4];
    float* out = (float*)d_out;

    float* xn;  cudaGetSymbolAddress((void**)&xn,  g_xn);
    float* h;   cudaGetSymbolAddress((void**)&h,   g_h);
    float* ap;  cudaGetSymbolAddress((void**)&ap,  g_ap);
    __half *a1, *w1, *a2, *w2, *q16, *k16, *vT;
    cudaGetSymbolAddress((void**)&a1,  g_a1);
    cudaGetSymbolAddress((void**)&w1,  g_w1);
    cudaGetSymbolAddress((void**)&a2,  g_a2);
    cudaGetSymbolAddress((void**)&w2,  g_w2);
    cudaGetSymbolAddress((void**)&q16, g_q16);
    cudaGetSymbolAddress((void**)&k16, g_k16);
    cudaGetSymbolAddress((void**)&vT,  g_vT);

    static cudaStream_t s2 = nullptr;
    static cudaEvent_t ev0 = nullptr, evLn = nullptr, evW1 = nullptr, ev2 = nullptr;
    if (s2 == nullptr) {
        cudaStreamCreateWithFlags(&s2, cudaStreamNonBlocking);
        cudaEventCreateWithFlags(&ev0,  cudaEventDisableTiming);
        cudaEventCreateWithFlags(&evLn, cudaEventDisableTiming);
        cudaEventCreateWithFlags(&evW1, cudaEventDisableTiming);
        cudaEventCreateWithFlags(&ev2,  cudaEventDisableTiming);
    }

    const int SMEM = NSTAGE * STAGEB;   // 81920 -> 2 CTAs/SM
    cudaFuncSetAttribute(gemm_mma<0>, cudaFuncAttributeMaxDynamicSharedMemorySize, SMEM);
    cudaFuncSetAttribute(gemm_mma<1>, cudaFuncAttributeMaxDynamicSharedMemorySize, SMEM);

    // fork
    cudaEventRecord(ev0, 0);
    cudaStreamWaitEvent(s2, ev0, 0);

    // s2: ln -> tsplit_w2 -> gemm1_ffn -> gemm2_ffn
    ln_split_kernel<<<MTOK, 256, 0, s2>>>(x, gamma, beta, xn, a1);
    cudaEventRecord(evLn, s2);
    tsplit_kernel<<<dim3(DIM/64, OUTK/64), dim3(16, 16), 0, s2>>>(W_out, DIM, w2, OUTK);

    // main: tsplit_w1
    tsplit_kernel<<<dim3(HCOLS/64, DIM/64), dim3(16, 16)>>>(W_in, LDWIN, w1, DIM);
    cudaEventRecord(evW1, 0);

    // s2 continues: gemm1 ffn slice (needs a1 [same stream] + w1 [evW1])
    cudaStreamWaitEvent(s2, evW1, 0);
    gemm_mma<0><<<dim3(MTOK/128, (HCOLS - QKV)/128), 256, SMEM, s2>>>(
        a1, w1, nullptr, a2, DIM, DIM, 0, QKV, nullptr);
    gemm_mma<1><<<dim3(MTOK/128, DIM/128), 256, SMEM, s2>>>(
        a2 + 2048, w2 + 2048, out, nullptr, OUTK - 2048, OUTK, DIM, 0, xn);
    cudaEventRecord(ev2, s2);

    // main: gemm1 qkv slice (needs w1 [same stream] + a1 [evLn]),
    // then attention chain + attn slice of GEMM2 into ap.
    cudaStreamWaitEvent(0, evLn, 0);
    gemm_mma<0><<<dim3(MTOK/128, QKV/128), 256, SMEM>>>(
        a1, w1, h, nullptr, DIM, DIM, QKV, 0, nullptr);
    qkv_prep_kernel<<<MTOK, 128>>>(h, q16, k16, vT);
    fmha_kernel<<<dim3(SEQ/64, NHEAD, BATCH), 128>>>(q16, k16, vT, a2);
    gemm_mma<0><<<dim3(MTOK/128, 2048/128), 256, SMEM>>>(
        a2, w2, ap, nullptr, 2048, OUTK, DIM, 0, nullptr);

    // join: out += ap
    cudaStreamWaitEvent(0, ev2, 0);
    add_kernel<<<(MTOK * DIM) / 1024, 256>>>(out, ap);
}

// round 15
// speedup vs baseline: 1.4228x; 1.4228x over previous
#include <cuda_runtime.h>
#include <cuda_fp16.h>
#include <math.h>
#include <stdint.h>

// ---------------------------------------------------------------------------
// Problem constants
// ---------------------------------------------------------------------------
#define BATCH 2
#define SEQ   2048
#define DIM   2048
#define NHEAD 32
#define DHEAD 64
#define FFN   8192
#define LDWIN 18560
#define HCOLS 10368
#define QKV   2176
#define OUTK  10240
#define MTOK  (BATCH*SEQ)
#define LN_EPS 1e-5f
#define QSCALE 0.125f
#define LOG2E  1.4426950408889634f

// ---------------------------------------------------------------------------
// Scratch (device globals)
// ---------------------------------------------------------------------------
__device__ float g_xn[(size_t)MTOK * DIM];
__device__ float g_h[(size_t)MTOK * QKV];
__device__ float g_ap[(size_t)MTOK * DIM];      // attn-slice partial of GEMM2
__device__ __half g_a1[(size_t)MTOK * DIM];
__device__ __half g_w1[(size_t)HCOLS * DIM];
__device__ __half g_a2[(size_t)MTOK * OUTK];
__device__ __half g_w2[(size_t)DIM * OUTK];
__device__ __half g_q16[(size_t)MTOK * DIM];
__device__ __half g_k16[(size_t)MTOK * DHEAD];
__device__ __half g_vT[(size_t)MTOK * DHEAD];

// ---------------------------------------------------------------------------
// PTX helpers
// ---------------------------------------------------------------------------
__device__ __forceinline__ uint32_t smem_u32(const void* p) {
    uint32_t a;
    asm("{ .reg .u64 t; cvta.to.shared.u64 t, %1; cvt.u32.u64 %0, t; }" : "=r"(a) : "l"(p));
    return a;
}
#define CP_ASYNC16(sa, gp) \
    asm volatile("cp.async.cg.shared.global [%0], [%1], 16;" :: "r"(sa), "l"(gp))
#define CP_COMMIT() asm volatile("cp.async.commit_group;" ::: "memory")
#define CP_WAIT(n)  asm volatile("cp.async.wait_group %0;" :: "n"(n) : "memory")

#define LDSM_X4(r0, r1, r2, r3, addr) \
    asm volatile("ldmatrix.sync.aligned.m8n8.x4.shared.b16 {%0,%1,%2,%3}, [%4];" \
        : "=r"(r0), "=r"(r1), "=r"(r2), "=r"(r3) : "r"(addr))

#define MMA16816(d, a0, a1, a2, a3, b0, b1) \
    asm volatile("mma.sync.aligned.m16n8k16.row.col.f32.f16.f16.f32 " \
        "{%0,%1,%2,%3}, {%4,%5,%6,%7}, {%8,%9}, {%0,%1,%2,%3};" \
        : "+f"((d)[0]), "+f"((d)[1]), "+f"((d)[2]), "+f"((d)[3]) \
        : "r"(a0), "r"(a1), "r"(a2), "r"(a3), "r"(b0), "r"(b1))

__device__ __forceinline__ __half2 h2(float x, float y) {
    return __halves2half2(__float2half_rn(x), __float2half_rn(y));
}
__device__ __forceinline__ uint32_t packh2(float x, float y) {
    __half2 v = __floats2half2_rn(x, y);
    return *reinterpret_cast<uint32_t*>(&v);
}

__device__ __forceinline__ float exp2_poly(float t) {
    t = fmaxf(t, -60.0f);
    float fi = floorf(t);
    float f = t - fi;
    float p = 1.3333558e-3f;
    p = fmaf(p, f, 9.6181291e-3f);
    p = fmaf(p, f, 5.5504109e-2f);
    p = fmaf(p, f, 2.4022651e-1f);
    p = fmaf(p, f, 6.9314718e-1f);
    p = fmaf(p, f, 1.0f);
    float s = __int_as_float(((int)fi + 127) << 23);
    return s * p;
}

// ---------------------------------------------------------------------------
// Kernel: LayerNorm -> xn (fp32 residual) + a1 (fp16 GEMM1 operand)
// ---------------------------------------------------------------------------
__global__ void ln_split_kernel(const float* __restrict__ x,
                                const float* __restrict__ gamma,
                                const float* __restrict__ beta,
                                float* __restrict__ xn,
                                __half* __restrict__ a1) {
    int row = blockIdx.x;
    int tid = threadIdx.x;
    const float4* xr = reinterpret_cast<const float4*>(x + (size_t)row * DIM);
    float4 a = xr[tid];
    float4 b = xr[tid + 256];
    float s  = a.x + a.y + a.z + a.w + b.x + b.y + b.z + b.w;
    float s2 = a.x*a.x + a.y*a.y + a.z*a.z + a.w*a.w
             + b.x*b.x + b.y*b.y + b.z*b.z + b.w*b.w;
    #pragma unroll
    for (int off = 16; off > 0; off >>= 1) {
        s  += __shfl_xor_sync(0xffffffffu, s,  off);
        s2 += __shfl_xor_sync(0xffffffffu, s2, off);
    }
    __shared__ float ss[8], ss2[8];
    int wid = tid >> 5, lane = tid & 31;
    if (lane == 0) { ss[wid] = s; ss2[wid] = s2; }
    __syncthreads();
    s  = ss[0] + ss[1] + ss[2] + ss[3] + ss[4] + ss[5] + ss[6] + ss[7];
    s2 = ss2[0]+ ss2[1]+ ss2[2]+ ss2[3]+ ss2[4]+ ss2[5]+ ss2[6]+ ss2[7];
    float mean = s * (1.0f / DIM);
    float var  = s2 * (1.0f / DIM) - mean * mean;
    float rstd = rsqrtf(var + LN_EPS);

    const float4* g4 = reinterpret_cast<const float4*>(gamma);
    const float4* b4 = reinterpret_cast<const float4*>(beta);
    float4 g0 = g4[tid], g1 = g4[tid + 256];
    float4 be0 = b4[tid], be1 = b4[tid + 256];
    float4 o0, o1;
    o0.x = (a.x - mean) * rstd * g0.x + be0.x;
    o0.y = (a.y - mean) * rstd * g0.y + be0.y;
    o0.z = (a.z - mean) * rstd * g0.z + be0.z;
    o0.w = (a.w - mean) * rstd * g0.w + be0.w;
    o1.x = (b.x - mean) * rstd * g1.x + be1.x;
    o1.y = (b.y - mean) * rstd * g1.y + be1.y;
    o1.z = (b.z - mean) * rstd * g1.z + be1.z;
    o1.w = (b.w - mean) * rstd * g1.w + be1.w;
    float4* o4 = reinterpret_cast<float4*>(xn + (size_t)row * DIM);
    o4[tid] = o0;
    o4[tid + 256] = o1;

    __half2* ph = reinterpret_cast<__half2*>(a1 + (size_t)row * DIM);
    ph[tid*2+0]   = h2(o0.x, o0.y);
    ph[tid*2+1]   = h2(o0.z, o0.w);
    ph[tid*2+512] = h2(o1.x, o1.y);
    ph[tid*2+513] = h2(o1.z, o1.w);
}

// ---------------------------------------------------------------------------
// Kernel: transpose + fp16 convert, 64x64 tile, vectorized.
// dst[n][k] = src[k][n]. Block (16,16).
// ---------------------------------------------------------------------------
__global__ void tsplit_kernel(const float* __restrict__ src, int ld_src,
                              __half* __restrict__ dst, int ld_dst) {
    __shared__ float t[64][65];
    int n0 = blockIdx.x * 64, k0 = blockIdx.y * 64;
    int tx = threadIdx.x, ty = threadIdx.y;    // 16 x 16
    #pragma unroll
    for (int i = 0; i < 4; i++) {
        float4 v = *reinterpret_cast<const float4*>(
            src + (size_t)(k0 + ty + 16*i) * ld_src + n0 + tx*4);
        t[ty + 16*i][tx*4+0] = v.x;
        t[ty + 16*i][tx*4+1] = v.y;
        t[ty + 16*i][tx*4+2] = v.z;
        t[ty + 16*i][tx*4+3] = v.w;
    }
    __syncthreads();
    #pragma unroll
    for (int i = 0; i < 4; i++) {
        int n = ty + 16*i;
        uint2 u;
        u.x = packh2(t[tx*4+0][n], t[tx*4+1][n]);
        u.y = packh2(t[tx*4+2][n], t[tx*4+3][n]);
        *reinterpret_cast<uint2*>(dst + (size_t)(n0 + n) * ld_dst + k0 + tx*4) = u;
    }
}

// ---------------------------------------------------------------------------
// Kernel: out += ap (fp32, vectorized)
// ---------------------------------------------------------------------------
__global__ void add_kernel(float* __restrict__ out, const float* __restrict__ ap) {
    size_t i = ((size_t)blockIdx.x * 256 + threadIdx.x) * 4;
    float4 o = *reinterpret_cast<float4*>(out + i);
    float4 a = *reinterpret_cast<const float4*>(ap + i);
    o.x += a.x; o.y += a.y; o.z += a.z; o.w += a.w;
    *reinterpret_cast<float4*>(out + i) = o;
}

// ---------------------------------------------------------------------------
// Tensor-core GEMM (R9 config: BK=32, SROWB=80, NSTAGE=4, 256 thr, 2 CTAs/SM).
// ld = row stride of A and B (elements); K = reduction extent.
// MODE 0: n0 <  QKV -> plain fp32 to Cf (ld ldc); else fp16 to Ch at col-128.
// MODE 1: fp32 out = acc + resid.
// ---------------------------------------------------------------------------
#define BK     32
#define SROWB  80
#define OFF_B  10240
#define STAGEB 20480
#define NSTAGE 4

template <int MODE>
__global__ __launch_bounds__(256, 2) void gemm_mma(
        const __half* __restrict__ A, const __half* __restrict__ B,
        float* __restrict__ Cf, __half* __restrict__ Ch,
        int K, int ld, int ldc, const float* __restrict__ resid) {
    extern __shared__ __align__(16) char dsm[];
    uint32_t sbase = smem_u32(dsm);

    int tid  = threadIdx.x;
    int wid  = tid >> 5;
    int lane = tid & 31;
    int wm   = wid & 3;
    int wn   = wid >> 2;

    int m0 = blockIdx.x * 128;
    int n0 = blockIdx.y * 128;

    uint32_t sO[2]; size_t gO[2];
    #pragma unroll
    for (int i = 0; i < 2; i++) {
        int idx = tid + i * 256;
        int row = idx >> 2, c = idx & 3;
        sO[i] = (uint32_t)(row * SROWB + c * 16);
        gO[i] = (size_t)row * ld + c * 8;
    }
    const __half* gA = A + (size_t)m0 * ld;
    const __half* gB = B + (size_t)n0 * ld;

    const int NC = K / BK;

    auto load_chunk = [&](int c) {
        uint32_t base = sbase + (uint32_t)(c % NSTAGE) * STAGEB;
        size_t co = (size_t)c * BK;
        #pragma unroll
        for (int i = 0; i < 2; i++) {
            CP_ASYNC16(base + sO[i],         (const void*)(gA + gO[i] + co));
            CP_ASYNC16(base + OFF_B + sO[i], (const void*)(gB + gO[i] + co));
        }
    };

    float acc[2][8][4];
    #pragma unroll
    for (int i = 0; i < 2; i++)
        #pragma unroll
        for (int j = 0; j < 8; j++)
            #pragma unroll
            for (int v = 0; v < 4; v++) acc[i][j][v] = 0.0f;

    #pragma unroll
    for (int c = 0; c < NSTAGE - 1; c++) { load_chunk(c); CP_COMMIT(); }

    uint32_t aBase = (uint32_t)((wm * 32 + (lane & 15)) * SROWB + (lane >> 4) * 16);
    uint32_t bBase = (uint32_t)((wn * 64 + (lane & 15)) * SROWB + (lane >> 4) * 16);

    for (int c = 0; c < NC; c++) {
        CP_WAIT(NSTAGE - 2);
        __syncthreads();
        if (c + NSTAGE - 1 < NC) load_chunk(c + NSTAGE - 1);
        CP_COMMIT();

        uint32_t buf = sbase + (uint32_t)(c % NSTAGE) * STAGEB;

        #pragma unroll
        for (int ks = 0; ks < 2; ks++) {
            uint32_t aF[2][4];
            #pragma unroll
            for (int mt = 0; mt < 2; mt++) {
                uint32_t ad = buf + aBase + mt * (16 * SROWB) + ks * 32;
                LDSM_X4(aF[mt][0], aF[mt][1], aF[mt][2], aF[mt][3], ad);
            }
            #pragma unroll
            for (int g = 0; g < 4; g++) {
                uint32_t bd = buf + OFF_B + bBase + g * (16 * SROWB) + ks * 32;
                uint32_t bf[4];
                LDSM_X4(bf[0], bf[1], bf[2], bf[3], bd);
                int nt0 = 2 * g, nt1 = 2 * g + 1;
                MMA16816(acc[0][nt0], aF[0][0], aF[0][1], aF[0][2], aF[0][3], bf[0], bf[2]);
                MMA16816(acc[0][nt1], aF[0][0], aF[0][1], aF[0][2], aF[0][3], bf[1], bf[3]);
                MMA16816(acc[1][nt0], aF[1][0], aF[1][1], aF[1][2], aF[1][3], bf[0], bf[2]);
                MMA16816(acc[1][nt1], aF[1][0], aF[1][1], aF[1][2], aF[1][3], bf[1], bf[3]);
            }
        }
    }

    int g = lane >> 2, q = lane & 3;
    if (MODE == 0 && n0 >= QKV) {
        #pragma unroll
        for (int mt = 0; mt < 2; mt++) {
            #pragma unroll
            for (int nt = 0; nt < 8; nt++) {
                int rowm = m0 + wm * 32 + mt * 16 + g;
                int coln = n0 - 128 + wn * 64 + nt * 8 + q * 2;
                *reinterpret_cast<__half2*>(Ch + (size_t)rowm * OUTK + coln) =
                    h2(acc[mt][nt][0], acc[mt][nt][1]);
                *reinterpret_cast<__half2*>(Ch + (size_t)(rowm + 8) * OUTK + coln) =
                    h2(acc[mt][nt][2], acc[mt][nt][3]);
            }
        }
        return;
    }
    #pragma unroll
    for (int mt = 0; mt < 2; mt++) {
        #pragma unroll
        for (int nt = 0; nt < 8; nt++) {
            int rowm = m0 + wm * 32 + mt * 16 + g;
            int coln = n0 + wn * 64 + nt * 8 + q * 2;
            float* p0 = Cf + (size_t)rowm * ldc + coln;
            float* p1 = Cf + (size_t)(rowm + 8) * ldc + coln;
            float2 v0 = make_float2(acc[mt][nt][0], acc[mt][nt][1]);
            float2 v1 = make_float2(acc[mt][nt][2], acc[mt][nt][3]);
            if (MODE == 1) {
                const float2 r0 = *reinterpret_cast<const float2*>(resid + (size_t)rowm * ldc + coln);
                const float2 r1 = *reinterpret_cast<const float2*>(resid + (size_t)(rowm + 8) * ldc + coln);
                v0.x += r0.x; v0.y += r0.y;
                v1.x += r1.x; v1.y += r1.y;
            }
            *reinterpret_cast<float2*>(p0) = v0;
            *reinterpret_cast<float2*>(p1) = v1;
        }
    }
}

// ---------------------------------------------------------------------------
// Kernel: qkv prep (sincos once per (s,c), shared across heads).
// ---------------------------------------------------------------------------
__global__ __launch_bounds__(128) void qkv_prep_kernel(
        const float* __restrict__ h,
        __half* __restrict__ q16, __half* __restrict__ k16,
        __half* __restrict__ vT) {
    __shared__ float scs[32], ssn[32];
    int row = blockIdx.x;
    int b = row >> 11;
    int s = row & (SEQ - 1);
    const float* hp = h + (size_t)row * QKV;
    int tid = threadIdx.x;

    if (tid < 32) {
        int c = tid;
        float inv = exp2f(-(float)c * (13.287712379549449f / 32.0f));
        float ang = (float)s * inv;
        float sn, cs;
        sincosf(ang, &sn, &cs);
        scs[c] = cs; ssn[c] = sn;
        float ka = hp[2048 + c], kb = hp[2048 + c + 32];
        __half* kd = k16 + ((size_t)b * SEQ + s) * DHEAD;
        kd[c]      = __float2half_rn(ka * cs - kb * sn);
        kd[c + 32] = __float2half_rn(kb * cs + ka * sn);
    }
    if (tid >= 64) {
        int d = tid - 64;
        vT[((size_t)b * DHEAD + d) * SEQ + s] = __float2half_rn(hp[2112 + d]);
    }
    __syncthreads();

    const float scl = QSCALE * LOG2E;
    for (int i = tid; i < 1024; i += 128) {
        int hd = i >> 5, c = i & 31;
        float cs = scs[c], sn = ssn[c];
        float qa = hp[hd * 64 + c], qb = hp[hd * 64 + c + 32];
        __half* qd = q16 + ((size_t)(b * NHEAD + hd) * SEQ + s) * DHEAD;
        qd[c]      = __float2half_rn((qa * cs - qb * sn) * scl);
        qd[c + 32] = __float2half_rn((qb * cs + qa * sn) * scl);
    }
}

// ---------------------------------------------------------------------------
// Tensor-core causal MQA flash attention (64-row Q tile).
// ---------------------------------------------------------------------------
#define FROWB 144

__global__ __launch_bounds__(128) void fmha_kernel(
        const __half* __restrict__ q16, const __half* __restrict__ k16,
        const __half* __restrict__ vT, __half* __restrict__ a2) {
    __shared__ __half sQ[64 * 72];
    __shared__ __half sK[2][64 * 72];
    __shared__ __half sV[2][64 * 72];

    int tid = threadIdx.x;
    int w = tid >> 5, lane = tid & 31;
    int g = lane >> 2, t = lane & 3;
    int qt = (int)gridDim.x - 1 - (int)blockIdx.x;
    int head = blockIdx.y;
    int b = blockIdx.z;

    const __half* gQ = q16 + ((size_t)(b * NHEAD + head) * SEQ + qt * 64) * DHEAD;
    const __half* gK = k16 + (size_t)b * SEQ * DHEAD;
    const __half* gV = vT + (size_t)b * DHEAD * SEQ;

    uint32_t sqa = smem_u32(sQ);
    uint32_t ska[2] = {smem_u32(sK[0]), smem_u32(sK[1])};
    uint32_t sva[2] = {smem_u32(sV[0]), smem_u32(sV[1])};

    auto load_kv = [&](int kt2, int buf2) {
        #pragma unroll
        for (int i = 0; i < 4; i++) {
            int idx = tid + i * 128;
            int r = idx >> 3, c = idx & 7;
            uint32_t so = (uint32_t)(r * FROWB + c * 16);
            CP_ASYNC16(ska[buf2] + so, (const void*)(gK + (size_t)(kt2 * 64 + r) * DHEAD + c * 8));
            CP_ASYNC16(sva[buf2] + so, (const void*)(gV + (size_t)r * SEQ + kt2 * 64 + c * 8));
        }
    };

    #pragma unroll
    for (int i = 0; i < 4; i++) {
        int idx = tid + i * 128;
        int r = idx >> 3, c = idx & 7;
        uint32_t so = (uint32_t)(r * FROWB + c * 16);
        CP_ASYNC16(sqa + so, (const void*)(gQ + (size_t)r * DHEAD + c * 8));
    }
    load_kv(0, 0);
    CP_COMMIT();
    CP_WAIT(0);
    __syncthreads();

    uint32_t aBase = (uint32_t)((w * 16 + (lane & 15)) * FROWB + (lane >> 4) * 16);
    uint32_t qa[4][4];
    #pragma unroll
    for (int ks = 0; ks < 4; ks++)
        LDSM_X4(qa[ks][0], qa[ks][1], qa[ks][2], qa[ks][3], sqa + aBase + ks * 32);

    uint32_t bBase = (uint32_t)((lane & 15) * FROWB + (lane >> 4) * 16);

    float o[8][4];
    #pragma unroll
    for (int n = 0; n < 8; n++)
        #pragma unroll
        for (int j = 0; j < 4; j++) o[n][j] = 0.0f;
    float m0 = -1e30f, m1 = -1e30f, l0 = 0.0f, l1 = 0.0f;

    for (int kt = 0; kt <= qt; kt++) {
        int buf = kt & 1;
        if (kt > 0) { CP_WAIT(0); __syncthreads(); }
        if (kt + 1 <= qt) { load_kv(kt + 1, buf ^ 1); CP_COMMIT(); }

        float s[8][4];
        #pragma unroll
        for (int n = 0; n < 8; n++)
            #pragma unroll
            for (int j = 0; j < 4; j++) s[n][j] = 0.0f;
        #pragma unroll
        for (int ng = 0; ng < 4; ng++) {
            #pragma unroll
            for (int ks = 0; ks < 4; ks++) {
                uint32_t bf[4];
                LDSM_X4(bf[0], bf[1], bf[2], bf[3],
                        ska[buf] + (uint32_t)(ng * 16 * FROWB) + bBase + ks * 32);
                MMA16816(s[2*ng],   qa[ks][0], qa[ks][1], qa[ks][2], qa[ks][3], bf[0], bf[2]);
                MMA16816(s[2*ng+1], qa[ks][0], qa[ks][1], qa[ks][2], qa[ks][3], bf[1], bf[3]);
            }
        }

        if (kt == qt) {
            int r0 = w * 16 + g;
            #pragma unroll
            for (int n = 0; n < 8; n++) {
                int c0 = n * 8 + 2 * t;
                if (c0 > r0)         s[n][0] = -1e30f;
                if (c0 + 1 > r0)     s[n][1] = -1e30f;
                if (c0 > r0 + 8)     s[n][2] = -1e30f;
                if (c0 + 1 > r0 + 8) s[n][3] = -1e30f;
            }
        }

        float tm0 = -1e30f, tm1 = -1e30f;
        #pragma unroll
        for (int n = 0; n < 8; n++) {
            tm0 = fmaxf(tm0, fmaxf(s[n][0], s[n][1]));
            tm1 = fmaxf(tm1, fmaxf(s[n][2], s[n][3]));
        }
        tm0 = fmaxf(tm0, __shfl_xor_sync(0xffffffffu, tm0, 1));
        tm0 = fmaxf(tm0, __shfl_xor_sync(0xffffffffu, tm0, 2));
        tm1 = fmaxf(tm1, __shfl_xor_sync(0xffffffffu, tm1, 1));
        tm1 = fmaxf(tm1, __shfl_xor_sync(0xffffffffu, tm1, 2));
        float mn0 = fmaxf(m0, tm0), mn1 = fmaxf(m1, tm1);
        float sc0 = exp2_poly(m0 - mn0), sc1 = exp2_poly(m1 - mn1);
        m0 = mn0; m1 = mn1;
        float ts0 = 0.0f, ts1 = 0.0f;
        #pragma unroll
        for (int n = 0; n < 8; n++) {
            s[n][0] = exp2_poly(s[n][0] - mn0);
            s[n][1] = exp2_poly(s[n][1] - mn0);
            s[n][2] = exp2_poly(s[n][2] - mn1);
            s[n][3] = exp2_poly(s[n][3] - mn1);
            ts0 += s[n][0] + s[n][1];
            ts1 += s[n][2] + s[n][3];
        }
        ts0 += __shfl_xor_sync(0xffffffffu, ts0, 1);
        ts0 += __shfl_xor_sync(0xffffffffu, ts0, 2);
        ts1 += __shfl_xor_sync(0xffffffffu, ts1, 1);
        ts1 += __shfl_xor_sync(0xffffffffu, ts1, 2);
        l0 = l0 * sc0 + ts0;
        l1 = l1 * sc1 + ts1;
        #pragma unroll
        for (int n = 0; n < 8; n++) {
            o[n][0] *= sc0; o[n][1] *= sc0;
            o[n][2] *= sc1; o[n][3] *= sc1;
        }

        uint32_t pa[4][4];
        #pragma unroll
        for (int kk = 0; kk < 4; kk++) {
            pa[kk][0] = packh2(s[2*kk][0],   s[2*kk][1]);
            pa[kk][1] = packh2(s[2*kk][2],   s[2*kk][3]);
            pa[kk][2] = packh2(s[2*kk+1][0], s[2*kk+1][1]);
            pa[kk][3] = packh2(s[2*kk+1][2], s[2*kk+1][3]);
        }

        #pragma unroll
        for (int ng = 0; ng < 4; ng++) {
            #pragma unroll
            for (int kk = 0; kk < 4; kk++) {
                uint32_t bf[4];
                LDSM_X4(bf[0], bf[1], bf[2], bf[3],
                        sva[buf] + (uint32_t)(ng * 16 * FROWB) + bBase + kk * 32);
                MMA16816(o[2*ng],   pa[kk][0], pa[kk][1], pa[kk][2], pa[kk][3], bf[0], bf[2]);
                MMA16816(o[2*ng+1], pa[kk][0], pa[kk][1], pa[kk][2], pa[kk][3], bf[1], bf[3]);
            }
        }
    }

    float inv0 = 1.0f / l0, inv1 = 1.0f / l1;
    int row0 = qt * 64 + w * 16 + g;
    size_t t0 = ((size_t)b * SEQ + row0) * OUTK + head * 64;
    size_t t1 = t0 + (size_t)8 * OUTK;
    #pragma unroll
    for (int n = 0; n < 8; n++) {
        int coff = n * 8 + 2 * t;
        *reinterpret_cast<__half2*>(a2 + t0 + coff) = h2(o[n][0] * inv0, o[n][1] * inv0);
        *reinterpret_cast<__half2*>(a2 + t1 + coff) = h2(o[n][2] * inv1, o[n][3] * inv1);
    }
}

// ---------------------------------------------------------------------------
extern "C" void kernel_launch(void* const* d_in, const int* in_sizes, int n_in,
                              void* d_out, int out_size) {
    const float* x     = (const float*)d_in[0];
    const float* W_in  = (const float*)d_in[1];
    const float* W_out = (const float*)d_in[2];
    const float* gamma = (const float*)d_in[3];
    const float* beta  = (const float*)d_in[4];
    float* out = (float*)d_out;

    float* xn;  cudaGetSymbolAddress((void**)&xn,  g_xn);
    float* h;   cudaGetSymbolAddress((void**)&h,   g_h);
    float* ap;  cudaGetSymbolAddress((void**)&ap,  g_ap);
    __half *a1, *w1, *a2, *w2, *q16, *k16, *vT;
    cudaGetSymbolAddress((void**)&a1,  g_a1);
    cudaGetSymbolAddress((void**)&w1,  g_w1);
    cudaGetSymbolAddress((void**)&a2,  g_a2);
    cudaGetSymbolAddress((void**)&w2,  g_w2);
    cudaGetSymbolAddress((void**)&q16, g_q16);
    cudaGetSymbolAddress((void**)&k16, g_k16);
    cudaGetSymbolAddress((void**)&vT,  g_vT);

    static cudaStream_t s2 = nullptr;
    static cudaEvent_t ev0 = nullptr, ev1 = nullptr, ev2 = nullptr, ev3 = nullptr;
    if (s2 == nullptr) {
        cudaStreamCreateWithFlags(&s2, cudaStreamNonBlocking);
        cudaEventCreateWithFlags(&ev0, cudaEventDisableTiming);
        cudaEventCreateWithFlags(&ev1, cudaEventDisableTiming);
        cudaEventCreateWithFlags(&ev2, cudaEventDisableTiming);
        cudaEventCreateWithFlags(&ev3, cudaEventDisableTiming);
    }

    const int SMEM = NSTAGE * STAGEB;   // 81920 -> 2 CTAs/SM
    cudaFuncSetAttribute(gemm_mma<0>, cudaFuncAttributeMaxDynamicSharedMemorySize, SMEM);
    cudaFuncSetAttribute(gemm_mma<1>, cudaFuncAttributeMaxDynamicSharedMemorySize, SMEM);

    // fork: side stream runs ln (x only) then W_out transpose
    cudaEventRecord(ev0, 0);
    cudaStreamWaitEvent(s2, ev0, 0);
    ln_split_kernel<<<MTOK, 256, 0, s2>>>(x, gamma, beta, xn, a1);
    cudaEventRecord(ev3, s2);                       // a1/xn ready
    tsplit_kernel<<<dim3(DIM/64, OUTK/64), dim3(16, 16), 0, s2>>>(W_out, DIM, w2, OUTK);

    // main: W_in transpose (concurrent with ln), then GEMM1 after both
    tsplit_kernel<<<dim3(HCOLS/64, DIM/64), dim3(16, 16)>>>(W_in, LDWIN, w1, DIM);
    cudaStreamWaitEvent(0, ev3, 0);
    gemm_mma<0><<<dim3(MTOK/128, HCOLS/128), 256, SMEM>>>(
        a1, w1, h, a2, DIM, DIM, QKV, nullptr);

    // fork: ffn slice of GEMM2 (K=8192) on s2 — depends on gemm1 + w2 only
    cudaEventRecord(ev1, 0);
    cudaStreamWaitEvent(s2, ev1, 0);
    gemm_mma<1><<<dim3(MTOK/128, DIM/128), 256, SMEM, s2>>>(
        a2 + 2048, w2 + 2048, out, nullptr, OUTK - 2048, OUTK, DIM, xn);

    // main: attention chain, then attn slice of GEMM2 into side buffer.
    // Both overlap with gemm2_ffn on s2.
    qkv_prep_kernel<<<MTOK, 128>>>(h, q16, k16, vT);
    fmha_kernel<<<dim3(SEQ/64, NHEAD, BATCH), 128>>>(q16, k16, vT, a2);
    gemm_mma<0><<<dim3(MTOK/128, 2048/128), 256, SMEM>>>(
        a2, w2, ap, nullptr, 2048, OUTK, DIM, nullptr);

    // join: out += ap
    cudaEventRecord(ev2, s2);
    cudaStreamWaitEvent(0, ev2, 0);
    add_kernel<<<(MTOK * DIM) / 1024, 256>>>(out, ap);
}

// round 16
// speedup vs baseline: 1.4390x; 1.0114x over previous
#include <cuda_runtime.h>
#include <cuda_fp16.h>
#include <math.h>
#include <stdint.h>

// ---------------------------------------------------------------------------
// Problem constants
// ---------------------------------------------------------------------------
#define BATCH 2
#define SEQ   2048
#define DIM   2048
#define NHEAD 32
#define DHEAD 64
#define FFN   8192
#define LDWIN 18560
#define HCOLS 10368
#define QKV   2176
#define OUTK  10240
#define MTOK  (BATCH*SEQ)
#define LN_EPS 1e-5f
#define QSCALE 0.125f
#define LOG2E  1.4426950408889634f

// ---------------------------------------------------------------------------
// Scratch (device globals)
// ---------------------------------------------------------------------------
__device__ float g_xn[(size_t)MTOK * DIM];
__device__ float g_h[(size_t)MTOK * QKV];
__device__ __half g_a1[(size_t)MTOK * DIM];
__device__ __half g_w1[(size_t)HCOLS * DIM];
__device__ __half g_a2[(size_t)MTOK * OUTK];
__device__ __half g_w2[(size_t)DIM * OUTK];
__device__ __half g_q16[(size_t)MTOK * DIM];
__device__ __half g_k16[(size_t)MTOK * DHEAD];
__device__ __half g_vT[(size_t)MTOK * DHEAD];

// ---------------------------------------------------------------------------
// PTX helpers
// ---------------------------------------------------------------------------
__device__ __forceinline__ uint32_t smem_u32(const void* p) {
    uint32_t a;
    asm("{ .reg .u64 t; cvta.to.shared.u64 t, %1; cvt.u32.u64 %0, t; }" : "=r"(a) : "l"(p));
    return a;
}
#define CP_ASYNC16(sa, gp) \
    asm volatile("cp.async.cg.shared.global [%0], [%1], 16;" :: "r"(sa), "l"(gp))
#define CP_COMMIT() asm volatile("cp.async.commit_group;" ::: "memory")
#define CP_WAIT(n)  asm volatile("cp.async.wait_group %0;" :: "n"(n) : "memory")

#define LDSM_X4(r0, r1, r2, r3, addr) \
    asm volatile("ldmatrix.sync.aligned.m8n8.x4.shared.b16 {%0,%1,%2,%3}, [%4];" \
        : "=r"(r0), "=r"(r1), "=r"(r2), "=r"(r3) : "r"(addr))

#define MMA16816(d, a0, a1, a2, a3, b0, b1) \
    asm volatile("mma.sync.aligned.m16n8k16.row.col.f32.f16.f16.f32 " \
        "{%0,%1,%2,%3}, {%4,%5,%6,%7}, {%8,%9}, {%0,%1,%2,%3};" \
        : "+f"((d)[0]), "+f"((d)[1]), "+f"((d)[2]), "+f"((d)[3]) \
        : "r"(a0), "r"(a1), "r"(a2), "r"(a3), "r"(b0), "r"(b1))

#define REDADD_F32(p, v) \
    asm volatile("red.global.add.f32 [%0], %1;" :: "l"(p), "f"(v) : "memory")

__device__ __forceinline__ __half2 h2(float x, float y) {
    return __halves2half2(__float2half_rn(x), __float2half_rn(y));
}
__device__ __forceinline__ uint32_t packh2(float x, float y) {
    __half2 v = __floats2half2_rn(x, y);
    return *reinterpret_cast<uint32_t*>(&v);
}

__device__ __forceinline__ float exp2_poly(float t) {
    t = fmaxf(t, -60.0f);
    float fi = floorf(t);
    float f = t - fi;
    float p = 1.3333558e-3f;
    p = fmaf(p, f, 9.6181291e-3f);
    p = fmaf(p, f, 5.5504109e-2f);
    p = fmaf(p, f, 2.4022651e-1f);
    p = fmaf(p, f, 6.9314718e-1f);
    p = fmaf(p, f, 1.0f);
    float s = __int_as_float(((int)fi + 127) << 23);
    return s * p;
}

// ---------------------------------------------------------------------------
// Kernel: LayerNorm -> xn (fp32 residual) + a1 (fp16 GEMM1 operand)
// ---------------------------------------------------------------------------
__global__ void ln_split_kernel(const float* __restrict__ x,
                                const float* __restrict__ gamma,
                                const float* __restrict__ beta,
                                float* __restrict__ xn,
                                __half* __restrict__ a1) {
    int row = blockIdx.x;
    int tid = threadIdx.x;
    const float4* xr = reinterpret_cast<const float4*>(x + (size_t)row * DIM);
    float4 a = xr[tid];
    float4 b = xr[tid + 256];
    float s  = a.x + a.y + a.z + a.w + b.x + b.y + b.z + b.w;
    float s2 = a.x*a.x + a.y*a.y + a.z*a.z + a.w*a.w
             + b.x*b.x + b.y*b.y + b.z*b.z + b.w*b.w;
    #pragma unroll
    for (int off = 16; off > 0; off >>= 1) {
        s  += __shfl_xor_sync(0xffffffffu, s,  off);
        s2 += __shfl_xor_sync(0xffffffffu, s2, off);
    }
    __shared__ float ss[8], ss2[8];
    int wid = tid >> 5, lane = tid & 31;
    if (lane == 0) { ss[wid] = s; ss2[wid] = s2; }
    __syncthreads();
    s  = ss[0] + ss[1] + ss[2] + ss[3] + ss[4] + ss[5] + ss[6] + ss[7];
    s2 = ss2[0]+ ss2[1]+ ss2[2]+ ss2[3]+ ss2[4]+ ss2[5]+ ss2[6]+ ss2[7];
    float mean = s * (1.0f / DIM);
    float var  = s2 * (1.0f / DIM) - mean * mean;
    float rstd = rsqrtf(var + LN_EPS);

    const float4* g4 = reinterpret_cast<const float4*>(gamma);
    const float4* b4 = reinterpret_cast<const float4*>(beta);
    float4 g0 = g4[tid], g1 = g4[tid + 256];
    float4 be0 = b4[tid], be1 = b4[tid + 256];
    float4 o0, o1;
    o0.x = (a.x - mean) * rstd * g0.x + be0.x;
    o0.y = (a.y - mean) * rstd * g0.y + be0.y;
    o0.z = (a.z - mean) * rstd * g0.z + be0.z;
    o0.w = (a.w - mean) * rstd * g0.w + be0.w;
    o1.x = (b.x - mean) * rstd * g1.x + be1.x;
    o1.y = (b.y - mean) * rstd * g1.y + be1.y;
    o1.z = (b.z - mean) * rstd * g1.z + be1.z;
    o1.w = (b.w - mean) * rstd * g1.w + be1.w;
    float4* o4 = reinterpret_cast<float4*>(xn + (size_t)row * DIM);
    o4[tid] = o0;
    o4[tid + 256] = o1;

    __half2* ph = reinterpret_cast<__half2*>(a1 + (size_t)row * DIM);
    ph[tid*2+0]   = h2(o0.x, o0.y);
    ph[tid*2+1]   = h2(o0.z, o0.w);
    ph[tid*2+512] = h2(o1.x, o1.y);
    ph[tid*2+513] = h2(o1.z, o1.w);
}

// ---------------------------------------------------------------------------
// Kernel: transpose + fp16 convert, 64x64 tile, vectorized.
// ---------------------------------------------------------------------------
__global__ void tsplit_kernel(const float* __restrict__ src, int ld_src,
                              __half* __restrict__ dst, int ld_dst) {
    __shared__ float t[64][65];
    int n0 = blockIdx.x * 64, k0 = blockIdx.y * 64;
    int tx = threadIdx.x, ty = threadIdx.y;    // 16 x 16
    #pragma unroll
    for (int i = 0; i < 4; i++) {
        float4 v = *reinterpret_cast<const float4*>(
            src + (size_t)(k0 + ty + 16*i) * ld_src + n0 + tx*4);
        t[ty + 16*i][tx*4+0] = v.x;
        t[ty + 16*i][tx*4+1] = v.y;
        t[ty + 16*i][tx*4+2] = v.z;
        t[ty + 16*i][tx*4+3] = v.w;
    }
    __syncthreads();
    #pragma unroll
    for (int i = 0; i < 4; i++) {
        int n = ty + 16*i;
        uint2 u;
        u.x = packh2(t[tx*4+0][n], t[tx*4+1][n]);
        u.y = packh2(t[tx*4+2][n], t[tx*4+3][n]);
        *reinterpret_cast<uint2*>(dst + (size_t)(n0 + n) * ld_dst + k0 + tx*4) = u;
    }
}

// ---------------------------------------------------------------------------
// Kernel: out = xn (fp32 copy; accumulator base for the red.add epilogues)
// ---------------------------------------------------------------------------
__global__ void copy_kernel(float* __restrict__ out, const float* __restrict__ xn) {
    size_t i = ((size_t)blockIdx.x * 256 + threadIdx.x) * 4;
    *reinterpret_cast<float4*>(out + i) = *reinterpret_cast<const float4*>(xn + i);
}

// ---------------------------------------------------------------------------
// Tensor-core GEMM (R9 config: BK=32, SROWB=80, NSTAGE=4, 256 thr, 2 CTAs/SM).
// MODE 0: n0 <  QKV -> plain fp32 to Cf (ld ldc); else fp16 to Ch at col-128.
// MODE 2: red.global.add.f32 of acc into Cf (out pre-initialized to xn).
// ---------------------------------------------------------------------------
#define BK     32
#define SROWB  80
#define OFF_B  10240
#define STAGEB 20480
#define NSTAGE 4

template <int MODE>
__global__ __launch_bounds__(256, 2) void gemm_mma(
        const __half* __restrict__ A, const __half* __restrict__ B,
        float* __restrict__ Cf, __half* __restrict__ Ch,
        int K, int ld, int ldc) {
    extern __shared__ __align__(16) char dsm[];
    uint32_t sbase = smem_u32(dsm);

    int tid  = threadIdx.x;
    int wid  = tid >> 5;
    int lane = tid & 31;
    int wm   = wid & 3;
    int wn   = wid >> 2;

    int m0 = blockIdx.x * 128;
    int n0 = blockIdx.y * 128;

    uint32_t sO[2]; size_t gO[2];
    #pragma unroll
    for (int i = 0; i < 2; i++) {
        int idx = tid + i * 256;
        int row = idx >> 2, c = idx & 3;
        sO[i] = (uint32_t)(row * SROWB + c * 16);
        gO[i] = (size_t)row * ld + c * 8;
    }
    const __half* gA = A + (size_t)m0 * ld;
    const __half* gB = B + (size_t)n0 * ld;

    const int NC = K / BK;

    auto load_chunk = [&](int c) {
        uint32_t base = sbase + (uint32_t)(c % NSTAGE) * STAGEB;
        size_t co = (size_t)c * BK;
        #pragma unroll
        for (int i = 0; i < 2; i++) {
            CP_ASYNC16(base + sO[i],         (const void*)(gA + gO[i] + co));
            CP_ASYNC16(base + OFF_B + sO[i], (const void*)(gB + gO[i] + co));
        }
    };

    float acc[2][8][4];
    #pragma unroll
    for (int i = 0; i < 2; i++)
        #pragma unroll
        for (int j = 0; j < 8; j++)
            #pragma unroll
            for (int v = 0; v < 4; v++) acc[i][j][v] = 0.0f;

    #pragma unroll
    for (int c = 0; c < NSTAGE - 1; c++) { load_chunk(c); CP_COMMIT(); }

    uint32_t aBase = (uint32_t)((wm * 32 + (lane & 15)) * SROWB + (lane >> 4) * 16);
    uint32_t bBase = (uint32_t)((wn * 64 + (lane & 15)) * SROWB + (lane >> 4) * 16);

    for (int c = 0; c < NC; c++) {
        CP_WAIT(NSTAGE - 2);
        __syncthreads();
        if (c + NSTAGE - 1 < NC) load_chunk(c + NSTAGE - 1);
        CP_COMMIT();

        uint32_t buf = sbase + (uint32_t)(c % NSTAGE) * STAGEB;

        #pragma unroll
        for (int ks = 0; ks < 2; ks++) {
            uint32_t aF[2][4];
            #pragma unroll
            for (int mt = 0; mt < 2; mt++) {
                uint32_t ad = buf + aBase + mt * (16 * SROWB) + ks * 32;
                LDSM_X4(aF[mt][0], aF[mt][1], aF[mt][2], aF[mt][3], ad);
            }
            #pragma unroll
            for (int g = 0; g < 4; g++) {
                uint32_t bd = buf + OFF_B + bBase + g * (16 * SROWB) + ks * 32;
                uint32_t bf[4];
                LDSM_X4(bf[0], bf[1], bf[2], bf[3], bd);
                int nt0 = 2 * g, nt1 = 2 * g + 1;
                MMA16816(acc[0][nt0], aF[0][0], aF[0][1], aF[0][2], aF[0][3], bf[0], bf[2]);
                MMA16816(acc[0][nt1], aF[0][0], aF[0][1], aF[0][2], aF[0][3], bf[1], bf[3]);
                MMA16816(acc[1][nt0], aF[1][0], aF[1][1], aF[1][2], aF[1][3], bf[0], bf[2]);
                MMA16816(acc[1][nt1], aF[1][0], aF[1][1], aF[1][2], aF[1][3], bf[1], bf[3]);
            }
        }
    }

    int g = lane >> 2, q = lane & 3;
    if (MODE == 0 && n0 >= QKV) {
        #pragma unroll
        for (int mt = 0; mt < 2; mt++) {
            #pragma unroll
            for (int nt = 0; nt < 8; nt++) {
                int rowm = m0 + wm * 32 + mt * 16 + g;
                int coln = n0 - 128 + wn * 64 + nt * 8 + q * 2;
                *reinterpret_cast<__half2*>(Ch + (size_t)rowm * OUTK + coln) =
                    h2(acc[mt][nt][0], acc[mt][nt][1]);
                *reinterpret_cast<__half2*>(Ch + (size_t)(rowm + 8) * OUTK + coln) =
                    h2(acc[mt][nt][2], acc[mt][nt][3]);
            }
        }
        return;
    }
    #pragma unroll
    for (int mt = 0; mt < 2; mt++) {
        #pragma unroll
        for (int nt = 0; nt < 8; nt++) {
            int rowm = m0 + wm * 32 + mt * 16 + g;
            int coln = n0 + wn * 64 + nt * 8 + q * 2;
            float* p0 = Cf + (size_t)rowm * ldc + coln;
            float* p1 = Cf + (size_t)(rowm + 8) * ldc + coln;
            if (MODE == 2) {
                REDADD_F32(p0,     acc[mt][nt][0]);
                REDADD_F32(p0 + 1, acc[mt][nt][1]);
                REDADD_F32(p1,     acc[mt][nt][2]);
                REDADD_F32(p1 + 1, acc[mt][nt][3]);
            } else {
                *reinterpret_cast<float2*>(p0) = make_float2(acc[mt][nt][0], acc[mt][nt][1]);
                *reinterpret_cast<float2*>(p1) = make_float2(acc[mt][nt][2], acc[mt][nt][3]);
            }
        }
    }
}

// ---------------------------------------------------------------------------
// Kernel: qkv prep (sincos once per (s,c), shared across heads).
// ---------------------------------------------------------------------------
__global__ __launch_bounds__(128) void qkv_prep_kernel(
        const float* __restrict__ h,
        __half* __restrict__ q16, __half* __restrict__ k16,
        __half* __restrict__ vT) {
    __shared__ float scs[32], ssn[32];
    int row = blockIdx.x;
    int b = row >> 11;
    int s = row & (SEQ - 1);
    const float* hp = h + (size_t)row * QKV;
    int tid = threadIdx.x;

    if (tid < 32) {
        int c = tid;
        float inv = exp2f(-(float)c * (13.287712379549449f / 32.0f));
        float ang = (float)s * inv;
        float sn, cs;
        sincosf(ang, &sn, &cs);
        scs[c] = cs; ssn[c] = sn;
        float ka = hp[2048 + c], kb = hp[2048 + c + 32];
        __half* kd = k16 + ((size_t)b * SEQ + s) * DHEAD;
        kd[c]      = __float2half_rn(ka * cs - kb * sn);
        kd[c + 32] = __float2half_rn(kb * cs + ka * sn);
    }
    if (tid >= 64) {
        int d = tid - 64;
        vT[((size_t)b * DHEAD + d) * SEQ + s] = __float2half_rn(hp[2112 + d]);
    }
    __syncthreads();

    const float scl = QSCALE * LOG2E;
    for (int i = tid; i < 1024; i += 128) {
        int hd = i >> 5, c = i & 31;
        float cs = scs[c], sn = ssn[c];
        float qa = hp[hd * 64 + c], qb = hp[hd * 64 + c + 32];
        __half* qd = q16 + ((size_t)(b * NHEAD + hd) * SEQ + s) * DHEAD;
        qd[c]      = __float2half_rn((qa * cs - qb * sn) * scl);
        qd[c + 32] = __float2half_rn((qb * cs + qa * sn) * scl);
    }
}

// ---------------------------------------------------------------------------
// Tensor-core causal MQA flash attention (64-row Q tile).
// ---------------------------------------------------------------------------
#define FROWB 144

__global__ __launch_bounds__(128) void fmha_kernel(
        const __half* __restrict__ q16, const __half* __restrict__ k16,
        const __half* __restrict__ vT, __half* __restrict__ a2) {
    __shared__ __half sQ[64 * 72];
    __shared__ __half sK[2][64 * 72];
    __shared__ __half sV[2][64 * 72];

    int tid = threadIdx.x;
    int w = tid >> 5, lane = tid & 31;
    int g = lane >> 2, t = lane & 3;
    int qt = (int)gridDim.x - 1 - (int)blockIdx.x;
    int head = blockIdx.y;
    int b = blockIdx.z;

    const __half* gQ = q16 + ((size_t)(b * NHEAD + head) * SEQ + qt * 64) * DHEAD;
    const __half* gK = k16 + (size_t)b * SEQ * DHEAD;
    const __half* gV = vT + (size_t)b * DHEAD * SEQ;

    uint32_t sqa = smem_u32(sQ);
    uint32_t ska[2] = {smem_u32(sK[0]), smem_u32(sK[1])};
    uint32_t sva[2] = {smem_u32(sV[0]), smem_u32(sV[1])};

    auto load_kv = [&](int kt2, int buf2) {
        #pragma unroll
        for (int i = 0; i < 4; i++) {
            int idx = tid + i * 128;
            int r = idx >> 3, c = idx & 7;
            uint32_t so = (uint32_t)(r * FROWB + c * 16);
            CP_ASYNC16(ska[buf2] + so, (const void*)(gK + (size_t)(kt2 * 64 + r) * DHEAD + c * 8));
            CP_ASYNC16(sva[buf2] + so, (const void*)(gV + (size_t)r * SEQ + kt2 * 64 + c * 8));
        }
    };

    #pragma unroll
    for (int i = 0; i < 4; i++) {
        int idx = tid + i * 128;
        int r = idx >> 3, c = idx & 7;
        uint32_t so = (uint32_t)(r * FROWB + c * 16);
        CP_ASYNC16(sqa + so, (const void*)(gQ + (size_t)r * DHEAD + c * 8));
    }
    load_kv(0, 0);
    CP_COMMIT();
    CP_WAIT(0);
    __syncthreads();

    uint32_t aBase = (uint32_t)((w * 16 + (lane & 15)) * FROWB + (lane >> 4) * 16);
    uint32_t qa[4][4];
    #pragma unroll
    for (int ks = 0; ks < 4; ks++)
        LDSM_X4(qa[ks][0], qa[ks][1], qa[ks][2], qa[ks][3], sqa + aBase + ks * 32);

    uint32_t bBase = (uint32_t)((lane & 15) * FROWB + (lane >> 4) * 16);

    float o[8][4];
    #pragma unroll
    for (int n = 0; n < 8; n++)
        #pragma unroll
        for (int j = 0; j < 4; j++) o[n][j] = 0.0f;
    float m0 = -1e30f, m1 = -1e30f, l0 = 0.0f, l1 = 0.0f;

    for (int kt = 0; kt <= qt; kt++) {
        int buf = kt & 1;
        if (kt > 0) { CP_WAIT(0); __syncthreads(); }
        if (kt + 1 <= qt) { load_kv(kt + 1, buf ^ 1); CP_COMMIT(); }

        float s[8][4];
        #pragma unroll
        for (int n = 0; n < 8; n++)
            #pragma unroll
            for (int j = 0; j < 4; j++) s[n][j] = 0.0f;
        #pragma unroll
        for (int ng = 0; ng < 4; ng++) {
            #pragma unroll
            for (int ks = 0; ks < 4; ks++) {
                uint32_t bf[4];
                LDSM_X4(bf[0], bf[1], bf[2], bf[3],
                        ska[buf] + (uint32_t)(ng * 16 * FROWB) + bBase + ks * 32);
                MMA16816(s[2*ng],   qa[ks][0], qa[ks][1], qa[ks][2], qa[ks][3], bf[0], bf[2]);
                MMA16816(s[2*ng+1], qa[ks][0], qa[ks][1], qa[ks][2], qa[ks][3], bf[1], bf[3]);
            }
        }

        if (kt == qt) {
            int r0 = w * 16 + g;
            #pragma unroll
            for (int n = 0; n < 8; n++) {
                int c0 = n * 8 + 2 * t;
                if (c0 > r0)         s[n][0] = -1e30f;
                if (c0 + 1 > r0)     s[n][1] = -1e30f;
                if (c0 > r0 + 8)     s[n][2] = -1e30f;
                if (c0 + 1 > r0 + 8) s[n][3] = -1e30f;
            }
        }

        float tm0 = -1e30f, tm1 = -1e30f;
        #pragma unroll
        for (int n = 0; n < 8; n++) {
            tm0 = fmaxf(tm0, fmaxf(s[n][0], s[n][1]));
            tm1 = fmaxf(tm1, fmaxf(s[n][2], s[n][3]));
        }
        tm0 = fmaxf(tm0, __shfl_xor_sync(0xffffffffu, tm0, 1));
        tm0 = fmaxf(tm0, __shfl_xor_sync(0xffffffffu, tm0, 2));
        tm1 = fmaxf(tm1, __shfl_xor_sync(0xffffffffu, tm1, 1));
        tm1 = fmaxf(tm1, __shfl_xor_sync(0xffffffffu, tm1, 2));
        float mn0 = fmaxf(m0, tm0), mn1 = fmaxf(m1, tm1);
        float sc0 = exp2_poly(m0 - mn0), sc1 = exp2_poly(m1 - mn1);
        m0 = mn0; m1 = mn1;
        float ts0 = 0.0f, ts1 = 0.0f;
        #pragma unroll
        for (int n = 0; n < 8; n++) {
            s[n][0] = exp2_poly(s[n][0] - mn0);
            s[n][1] = exp2_poly(s[n][1] - mn0);
            s[n][2] = exp2_poly(s[n][2] - mn1);
            s[n][3] = exp2_poly(s[n][3] - mn1);
            ts0 += s[n][0] + s[n][1];
            ts1 += s[n][2] + s[n][3];
        }
        ts0 += __shfl_xor_sync(0xffffffffu, ts0, 1);
        ts0 += __shfl_xor_sync(0xffffffffu, ts0, 2);
        ts1 += __shfl_xor_sync(0xffffffffu, ts1, 1);
        ts1 += __shfl_xor_sync(0xffffffffu, ts1, 2);
        l0 = l0 * sc0 + ts0;
        l1 = l1 * sc1 + ts1;
        #pragma unroll
        for (int n = 0; n < 8; n++) {
            o[n][0] *= sc0; o[n][1] *= sc0;
            o[n][2] *= sc1; o[n][3] *= sc1;
        }

        uint32_t pa[4][4];
        #pragma unroll
        for (int kk = 0; kk < 4; kk++) {
            pa[kk][0] = packh2(s[2*kk][0],   s[2*kk][1]);
            pa[kk][1] = packh2(s[2*kk][2],   s[2*kk][3]);
            pa[kk][2] = packh2(s[2*kk+1][0], s[2*kk+1][1]);
            pa[kk][3] = packh2(s[2*kk+1][2], s[2*kk+1][3]);
        }

        #pragma unroll
        for (int ng = 0; ng < 4; ng++) {
            #pragma unroll
            for (int kk = 0; kk < 4; kk++) {
                uint32_t bf[4];
                LDSM_X4(bf[0], bf[1], bf[2], bf[3],
                        sva[buf] + (uint32_t)(ng * 16 * FROWB) + bBase + kk * 32);
                MMA16816(o[2*ng],   pa[kk][0], pa[kk][1], pa[kk][2], pa[kk][3], bf[0], bf[2]);
                MMA16816(o[2*ng+1], pa[kk][0], pa[kk][1], pa[kk][2], pa[kk][3], bf[1], bf[3]);
            }
        }
    }

    float inv0 = 1.0f / l0, inv1 = 1.0f / l1;
    int row0 = qt * 64 + w * 16 + g;
    size_t t0 = ((size_t)b * SEQ + row0) * OUTK + head * 64;
    size_t t1 = t0 + (size_t)8 * OUTK;
    #pragma unroll
    for (int n = 0; n < 8; n++) {
        int coff = n * 8 + 2 * t;
        *reinterpret_cast<__half2*>(a2 + t0 + coff) = h2(o[n][0] * inv0, o[n][1] * inv0);
        *reinterpret_cast<__half2*>(a2 + t1 + coff) = h2(o[n][2] * inv1, o[n][3] * inv1);
    }
}

// ---------------------------------------------------------------------------
extern "C" void kernel_launch(void* const* d_in, const int* in_sizes, int n_in,
                              void* d_out, int out_size) {
    const float* x     = (const float*)d_in[0];
    const float* W_in  = (const float*)d_in[1];
    const float* W_out = (const float*)d_in[2];
    const float* gamma = (const float*)d_in[3];
    const float* beta  = (const float*)d_in[4];
    float* out = (float*)d_out;

    float* xn;  cudaGetSymbolAddress((void**)&xn,  g_xn);
    float* h;   cudaGetSymbolAddress((void**)&h,   g_h);
    __half *a1, *w1, *a2, *w2, *q16, *k16, *vT;
    cudaGetSymbolAddress((void**)&a1,  g_a1);
    cudaGetSymbolAddress((void**)&w1,  g_w1);
    cudaGetSymbolAddress((void**)&a2,  g_a2);
    cudaGetSymbolAddress((void**)&w2,  g_w2);
    cudaGetSymbolAddress((void**)&q16, g_q16);
    cudaGetSymbolAddress((void**)&k16, g_k16);
    cudaGetSymbolAddress((void**)&vT,  g_vT);

    static cudaStream_t s2 = nullptr;
    static cudaEvent_t ev0 = nullptr, ev1 = nullptr, ev2 = nullptr,
                       ev3 = nullptr, evCp = nullptr;
    if (s2 == nullptr) {
        cudaStreamCreateWithFlags(&s2, cudaStreamNonBlocking);
        cudaEventCreateWithFlags(&ev0,  cudaEventDisableTiming);
        cudaEventCreateWithFlags(&ev1,  cudaEventDisableTiming);
        cudaEventCreateWithFlags(&ev2,  cudaEventDisableTiming);
        cudaEventCreateWithFlags(&ev3,  cudaEventDisableTiming);
        cudaEventCreateWithFlags(&evCp, cudaEventDisableTiming);
    }

    const int SMEM = NSTAGE * STAGEB;   // 81920 -> 2 CTAs/SM
    cudaFuncSetAttribute(gemm_mma<0>, cudaFuncAttributeMaxDynamicSharedMemorySize, SMEM);
    cudaFuncSetAttribute(gemm_mma<2>, cudaFuncAttributeMaxDynamicSharedMemorySize, SMEM);

    // fork: side stream runs ln -> out=xn copy -> W_out transpose
    cudaEventRecord(ev0, 0);
    cudaStreamWaitEvent(s2, ev0, 0);
    ln_split_kernel<<<MTOK, 256, 0, s2>>>(x, gamma, beta, xn, a1);
    cudaEventRecord(ev3, s2);                       // a1/xn ready
    copy_kernel<<<(MTOK * DIM) / 1024, 256, 0, s2>>>(out, xn);
    cudaEventRecord(evCp, s2);                      // out initialized
    tsplit_kernel<<<dim3(DIM/64, OUTK/64), dim3(16, 16), 0, s2>>>(W_out, DIM, w2, OUTK);

    // main: W_in transpose (concurrent with ln), then GEMM1 after both
    tsplit_kernel<<<dim3(HCOLS/64, DIM/64), dim3(16, 16)>>>(W_in, LDWIN, w1, DIM);
    cudaStreamWaitEvent(0, ev3, 0);
    gemm_mma<0><<<dim3(MTOK/128, HCOLS/128), 256, SMEM>>>(
        a1, w1, h, a2, DIM, DIM, QKV);

    // fork: ffn slice of GEMM2 (K=8192) on s2 — red.add into out
    cudaEventRecord(ev1, 0);
    cudaStreamWaitEvent(s2, ev1, 0);
    gemm_mma<2><<<dim3(MTOK/128, DIM/128), 256, SMEM, s2>>>(
        a2 + 2048, w2 + 2048, out, nullptr, OUTK - 2048, OUTK, DIM);

    // main: attention chain, then attn slice of GEMM2 — red.add into out
    qkv_prep_kernel<<<MTOK, 128>>>(h, q16, k16, vT);
    fmha_kernel<<<dim3(SEQ/64, NHEAD, BATCH), 128>>>(q16, k16, vT, a2);
    cudaStreamWaitEvent(0, evCp, 0);                // out base ready (long done)
    gemm_mma<2><<<dim3(MTOK/128, 2048/128), 256, SMEM>>>(
        a2, w2, out, nullptr, 2048, OUTK, DIM);

    // join: main stream waits for s2's gemm2_ffn before capture ends
    cudaEventRecord(ev2, s2);
    cudaStreamWaitEvent(0, ev2, 0);
}